// round 6
// baseline (speedup 1.0000x reference)
#include <cuda_runtime.h>
#include <math.h>
#include <stdint.h>

#define B_  4
#define S_  1024
#define D_  512
#define H_  8
#define DH_ 64
#define SCALE_ 0.125f   // DH^-0.5

typedef unsigned long long u64;

// Scratch (device globals: allocation-free per harness rules)
__device__ float g_Q[B_*H_*S_*DH_];
__device__ float g_K[B_*H_*S_*DH_];
__device__ float g_V[B_*H_*S_*DH_];
__device__ float g_C[B_*S_*D_];

// ---------------------------------------------------------------------------
// Packed f32x2 helpers (Blackwell) — used by attention
// ---------------------------------------------------------------------------
__device__ __forceinline__ u64 pack2(float lo, float hi) {
    u64 r; asm("mov.b64 %0, {%1, %2};" : "=l"(r) : "f"(lo), "f"(hi)); return r;
}
__device__ __forceinline__ u64 dup2(float x) { return pack2(x, x); }
__device__ __forceinline__ void unpack2(u64 v, float& lo, float& hi) {
    asm("mov.b64 {%0, %1}, %2;" : "=f"(lo), "=f"(hi) : "l"(v));
}
__device__ __forceinline__ u64 fma2(u64 a, u64 b, u64 c) {
    u64 d; asm("fma.rn.f32x2 %0, %1, %2, %3;" : "=l"(d) : "l"(a), "l"(b), "l"(c));
    return d;
}
__device__ __forceinline__ u64 add2(u64 a, u64 b) {
    u64 d; asm("add.rn.f32x2 %0, %1, %2;" : "=l"(d) : "l"(a), "l"(b)); return d;
}
__device__ __forceinline__ u64 mul2(u64 a, u64 b) {
    u64 d; asm("mul.rn.f32x2 %0, %1, %2;" : "=l"(d) : "l"(a), "l"(b)); return d;
}

// ---------------------------------------------------------------------------
// mma.sync tf32 helpers (baseline sm_80+ PTX — compiles at compute_103)
// ---------------------------------------------------------------------------
__device__ __forceinline__ uint32_t f2tf32(float v) {
    uint32_t t; asm("cvt.rna.tf32.f32 %0, %1;" : "=r"(t) : "f"(v)); return t;
}
__device__ __forceinline__ void mma_tf32(float* c, const uint32_t* a,
                                         const uint32_t* b) {
    asm volatile(
        "mma.sync.aligned.m16n8k8.row.col.f32.tf32.tf32.f32 "
        "{%0,%1,%2,%3}, {%4,%5,%6,%7}, {%8,%9}, {%0,%1,%2,%3};"
        : "+f"(c[0]), "+f"(c[1]), "+f"(c[2]), "+f"(c[3])
        : "r"(a[0]), "r"(a[1]), "r"(a[2]), "r"(a[3]), "r"(b[0]), "r"(b[1]));
}

// ===========================================================================
// Tensor-core tf32 GEMM via mma.sync: out[4096,512] = X[4096,512] @ W[512,512]
// 128x128 CTA tile, 8 warps x (64x32), m16n8k8 fragments.
// Smem holds A/B in FRAGMENT-PERMUTED tf32 layout:
//   Ap[buf][m_group(8)][k8(4)][lane(32)][reg(4)]  -> a-frag = one LDS.128
//   Bp[buf][n_group(16)][k8(4)][lane(32)][reg(2)] -> b-frag = one LDS.64
// headed=1 scatters out to [B,H,S,DH]; grid.z selects (X,W,O) triple.
// ===========================================================================
#define TCG_SMEM (2 * 4096 * 4 * 2)   // 65536 B (A: 32KB, B: 32KB)
__device__ __forceinline__ int ap_idx(int buf, int mg, int k8, int lane, int reg) {
    return (((buf * 8 + mg) * 4 + k8) * 32 + lane) * 4 + reg;
}
__device__ __forceinline__ int bp_idx(int buf, int ng, int k8, int lane, int reg) {
    return 8192 + (((buf * 16 + ng) * 4 + k8) * 32 + lane) * 2 + reg;
}

__global__ __launch_bounds__(256) void gemm_mma(
    const float* __restrict__ X0, const float* __restrict__ X1,
    const float* __restrict__ X2,
    const float* __restrict__ W0, const float* __restrict__ W1,
    const float* __restrict__ W2,
    float* __restrict__ O0, float* __restrict__ O1,
    float* __restrict__ O2, int headed)
{
    extern __shared__ __align__(16) uint32_t smu[];

    const int z = blockIdx.z;
    const float* X = (z == 0) ? X0 : (z == 1) ? X1 : X2;
    const float* W = (z == 0) ? W0 : (z == 1) ? W1 : W2;
    float* O       = (z == 0) ? O0 : (z == 1) ? O1 : O2;

    const int m0 = blockIdx.y * 128;
    const int n0 = blockIdx.x * 128;
    const int tid = threadIdx.x;
    const int wid = tid >> 5, lane = tid & 31;
    const int wm = wid & 1;        // 0..1 : 64-row block
    const int wn = wid >> 1;       // 0..3 : 32-col block

    float acc[4][4][4];
#pragma unroll
    for (int mt = 0; mt < 4; mt++)
#pragma unroll
        for (int nt = 0; nt < 4; nt++)
#pragma unroll
            for (int r = 0; r < 4; r++) acc[mt][nt][r] = 0.f;

    // loader coords
    const int la_row = tid >> 1;              // with it*? see loop: idx>>3
    (void)la_row;

    float4 ra[4], rb[4];

    // ---- prologue: chunk 0 -> buf 0
#pragma unroll
    for (int it = 0; it < 4; it++) {
        int idx = it * 256 + tid;
        int row = idx >> 3, q = idx & 7;
        ra[it] = *(const float4*)&X[(m0 + row) * 512 + q * 4];
        int k = idx >> 5, p = idx & 31;
        rb[it] = *(const float4*)&W[k * 512 + n0 + p * 4];
    }
#pragma unroll
    for (int it = 0; it < 4; it++) {
        int idx = it * 256 + tid;
        {   // A scatter
            int row = idx >> 3, q = idx & 7;
            int mg = row >> 4, k8 = q >> 1;
            int lb = (row & 7) * 4;
            int reg = ((row >> 3) & 1) + 2 * (q & 1);
            float v[4] = {ra[it].x, ra[it].y, ra[it].z, ra[it].w};
#pragma unroll
            for (int j = 0; j < 4; j++)
                smu[ap_idx(0, mg, k8, lb + j, reg)] = f2tf32(v[j]);
        }
        {   // B scatter
            int k = idx >> 5, p = idx & 31;
            int k8 = k >> 3, kin = k & 7, reg = kin >> 2;
            float v[4] = {rb[it].x, rb[it].y, rb[it].z, rb[it].w};
#pragma unroll
            for (int j = 0; j < 4; j++) {
                int n = 4 * p + j;
                smu[bp_idx(0, n >> 3, k8, (n & 7) * 4 + (kin & 3), reg)] = f2tf32(v[j]);
            }
        }
    }

    for (int c = 0; c < 16; c++) {
        __syncthreads();
        const int buf = c & 1;
        if (c < 15) {
            const int k0 = (c + 1) * 32;
#pragma unroll
            for (int it = 0; it < 4; it++) {
                int idx = it * 256 + tid;
                int row = idx >> 3, q = idx & 7;
                ra[it] = *(const float4*)&X[(m0 + row) * 512 + k0 + q * 4];
                int k = idx >> 5, p = idx & 31;
                rb[it] = *(const float4*)&W[(k0 + k) * 512 + n0 + p * 4];
            }
        }
        // ---- compute 4 k8-steps from buf
#pragma unroll
        for (int k8 = 0; k8 < 4; k8++) {
            uint32_t afr[4][4], bfr[4][2];
#pragma unroll
            for (int mt = 0; mt < 4; mt++) {
                uint4 v = *(const uint4*)&smu[ap_idx(buf, 4 * wm + mt, k8, lane, 0)];
                afr[mt][0] = v.x; afr[mt][1] = v.y; afr[mt][2] = v.z; afr[mt][3] = v.w;
            }
#pragma unroll
            for (int nt = 0; nt < 4; nt++) {
                uint2 v = *(const uint2*)&smu[bp_idx(buf, 4 * wn + nt, k8, lane, 0)];
                bfr[nt][0] = v.x; bfr[nt][1] = v.y;
            }
#pragma unroll
            for (int mt = 0; mt < 4; mt++)
#pragma unroll
                for (int nt = 0; nt < 4; nt++)
                    mma_tf32(acc[mt][nt], afr[mt], bfr[nt]);
        }
        // ---- store next chunk into other buf
        if (c < 15) {
            const int nb = (c + 1) & 1;
#pragma unroll
            for (int it = 0; it < 4; it++) {
                int idx = it * 256 + tid;
                {
                    int row = idx >> 3, q = idx & 7;
                    int mg = row >> 4, k8 = q >> 1;
                    int lb = (row & 7) * 4;
                    int reg = ((row >> 3) & 1) + 2 * (q & 1);
                    float v[4] = {ra[it].x, ra[it].y, ra[it].z, ra[it].w};
#pragma unroll
                    for (int j = 0; j < 4; j++)
                        smu[ap_idx(nb, mg, k8, lb + j, reg)] = f2tf32(v[j]);
                }
                {
                    int k = idx >> 5, p = idx & 31;
                    int k8 = k >> 3, kin = k & 7, reg = kin >> 2;
                    float v[4] = {rb[it].x, rb[it].y, rb[it].z, rb[it].w};
#pragma unroll
                    for (int j = 0; j < 4; j++) {
                        int n = 4 * p + j;
                        smu[bp_idx(nb, n >> 3, k8, (n & 7) * 4 + (kin & 3), reg)] = f2tf32(v[j]);
                    }
                }
            }
        }
    }

    // ---- epilogue: write C fragments
#pragma unroll
    for (int mt = 0; mt < 4; mt++) {
#pragma unroll
        for (int nt = 0; nt < 4; nt++) {
            int mrow = m0 + wm * 64 + mt * 16 + (lane >> 2);
            int ct = n0 + wn * 32 + nt * 8 + (lane & 3) * 2;
            float2 lo = make_float2(acc[mt][nt][0], acc[mt][nt][1]);
            float2 hi = make_float2(acc[mt][nt][2], acc[mt][nt][3]);
            if (headed) {
                int h0 = ct >> 6, dh = ct & 63;
                int bi = mrow >> 10, si = mrow & 1023;
                float* base = O + ((size_t)(bi * H_ + h0) * S_ * DH_) + dh;
                *(float2*)(base + (size_t)si * DH_) = lo;
                *(float2*)(base + (size_t)(si + 8) * DH_) = hi;
            } else {
                *(float2*)&O[(size_t)mrow * 512 + ct] = lo;
                *(float2*)&O[(size_t)(mrow + 8) * 512 + ct] = hi;
            }
        }
    }
}

// ===========================================================================
// Fused causal attention with skewed relative bias, f32x2 inner loops.
// bias(i,j) = q_i . rel[:, S-1-i+j]  for j <= i   (proven, unchanged)
// ===========================================================================
__device__ __forceinline__ float rmax16(float v) {
#pragma unroll
    for (int o = 8; o; o >>= 1) v = fmaxf(v, __shfl_xor_sync(0xffffffffu, v, o, 16));
    return v;
}
__device__ __forceinline__ float rsum16(float v) {
#pragma unroll
    for (int o = 8; o; o >>= 1) v += __shfl_xor_sync(0xffffffffu, v, o, 16);
    return v;
}

#define QS(d, i) Qs[(d) * 68 + (i)]
#define KS(d, j) Ks[(d) * 68 + (j)]
#define VS(j, d) Vs[(j) * 68 + (d)]
#define PS(i, j) Ps[(i) * 68 + (j)]
#define RS(d, l) Rs[(d) * 132 + (l)]
#define ATTN_SMEM_BYTES ((4 * 64 * 68 + 64 * 132) * 4)   // 103424 B

__global__ __launch_bounds__(256, 2) void attn_kernel(const float* __restrict__ Q,
                                                      const float* __restrict__ K,
                                                      const float* __restrict__ V,
                                                      const float* __restrict__ rel,
                                                      float* __restrict__ ctx)
{
    extern __shared__ __align__(16) float smf[];
    float* Qs = smf;
    float* Ks = Qs + 64 * 68;
    float* Vs = Ks + 64 * 68;
    float* Ps = Vs + 64 * 68;
    float* Rs = Ps + 64 * 68;

    const int qt = (int)gridDim.x - 1 - (int)blockIdx.x;
    const int h = blockIdx.y, b = blockIdx.z;
    const int i0 = qt * 64;
    const int tid = threadIdx.x;
    const int ty = tid >> 4, tx = tid & 15;

    const float* Qb = Q + (size_t)(b * H_ + h) * S_ * DH_;
    const float* Kb = K + (size_t)(b * H_ + h) * S_ * DH_;
    const float* Vb = V + (size_t)(b * H_ + h) * S_ * DH_;
    const float* relh = rel + (size_t)h * DH_ * S_;

#pragma unroll
    for (int rep = 0; rep < 4; rep++) {
        int lin = rep * 256 + tid;
        int i = lin >> 4, sd = (lin & 15) * 4;
        float4 v = *(const float4*)&Qb[(i0 + i) * DH_ + sd];
        QS(sd + 0, i) = v.x; QS(sd + 1, i) = v.y;
        QS(sd + 2, i) = v.z; QS(sd + 3, i) = v.w;
    }

    float mrow[4], lrow[4];
    u64 acc2[4][2];
#pragma unroll
    for (int r = 0; r < 4; r++) {
        mrow[r] = -1e30f;
        lrow[r] = 0.f;
        acc2[r][0] = 0ull; acc2[r][1] = 0ull;
    }

    const int bm3 = 60 + 4 * tx - 4 * ty;

    for (int jt = 0; jt <= qt; jt++) {
        const int j0 = jt * 64;
        __syncthreads();

#pragma unroll
        for (int rep = 0; rep < 4; rep++) {
            int lin = rep * 256 + tid;
            int j = lin >> 4, sd = (lin & 15) * 4;
            float4 kv = *(const float4*)&Kb[(j0 + j) * DH_ + sd];
            KS(sd + 0, j) = kv.x; KS(sd + 1, j) = kv.y;
            KS(sd + 2, j) = kv.z; KS(sd + 3, j) = kv.w;
            float4 vv = *(const float4*)&Vb[(j0 + j) * DH_ + sd];
            *(float4*)&VS(j, sd) = vv;
        }
        {
            const int cbase = S_ - 64 - i0 + j0;
#pragma unroll
            for (int rep = 0; rep < 32; rep++) {
                int lin = rep * 256 + tid;
                int d = lin >> 7, lc = lin & 127;
                int c = cbase + lc;
                RS(d, lc) = (c < S_) ? relh[d * S_ + c] : 0.f;
            }
        }
        __syncthreads();

        u64 s2[4][2];
#pragma unroll
        for (int r = 0; r < 4; r++) { s2[r][0] = 0ull; s2[r][1] = 0ull; }

#pragma unroll 4
        for (int d = 0; d < 64; d++) {
            float4 a4 = *(const float4*)&QS(d, ty * 4);
            ulonglong2 kk = *(const ulonglong2*)&Ks[d * 68 + tx * 4];
            float4 rA = *(const float4*)&Rs[d * 132 + bm3];
            float4 rB = *(const float4*)&Rs[d * 132 + bm3 + 4];
            u64 rvp[6];
            rvp[0] = pack2(rA.x, rA.y);
            rvp[1] = pack2(rA.y, rA.z);
            rvp[2] = pack2(rA.z, rA.w);
            rvp[3] = pack2(rA.w, rB.x);
            rvp[4] = pack2(rB.x, rB.y);
            rvp[5] = pack2(rB.y, rB.z);
            float av[4] = {a4.x, a4.y, a4.z, a4.w};
#pragma unroll
            for (int r = 0; r < 4; r++) {
                u64 ad = dup2(av[r]);
                s2[r][0] = fma2(ad, add2(kk.x, rvp[3 - r]), s2[r][0]);
                s2[r][1] = fma2(ad, add2(kk.y, rvp[5 - r]), s2[r][1]);
            }
        }

        float s[4][4];
#pragma unroll
        for (int r = 0; r < 4; r++) {
            unpack2(s2[r][0], s[r][0], s[r][1]);
            unpack2(s2[r][1], s[r][2], s[r][3]);
        }

#pragma unroll
        for (int r = 0; r < 4; r++) {
            int gi = i0 + ty * 4 + r;
#pragma unroll
            for (int c = 0; c < 4; c++) {
                int gj = j0 + tx * 4 + c;
                s[r][c] = (gj > gi) ? -INFINITY : s[r][c] * SCALE_;
            }
        }

#pragma unroll
        for (int r = 0; r < 4; r++) {
            float tm = fmaxf(fmaxf(s[r][0], s[r][1]), fmaxf(s[r][2], s[r][3]));
            tm = rmax16(tm);
            float nm = fmaxf(mrow[r], tm);
            float al = __expf(mrow[r] - nm);
            float p0 = __expf(s[r][0] - nm);
            float p1 = __expf(s[r][1] - nm);
            float p2 = __expf(s[r][2] - nm);
            float p3 = __expf(s[r][3] - nm);
            float rs = rsum16(p0 + p1 + p2 + p3);
            lrow[r] = lrow[r] * al + rs;
            mrow[r] = nm;
            u64 al2 = dup2(al);
            acc2[r][0] = mul2(acc2[r][0], al2);
            acc2[r][1] = mul2(acc2[r][1], al2);
            PS(ty * 4 + r, tx * 4 + 0) = p0;
            PS(ty * 4 + r, tx * 4 + 1) = p1;
            PS(ty * 4 + r, tx * 4 + 2) = p2;
            PS(ty * 4 + r, tx * 4 + 3) = p3;
        }
        __syncthreads();

#pragma unroll 8
        for (int j = 0; j < 64; j++) {
            float p_[4];
#pragma unroll
            for (int r = 0; r < 4; r++) p_[r] = PS(ty * 4 + r, j);
            ulonglong2 vv = *(const ulonglong2*)&Vs[j * 68 + tx * 4];
#pragma unroll
            for (int r = 0; r < 4; r++) {
                u64 pd = dup2(p_[r]);
                acc2[r][0] = fma2(pd, vv.x, acc2[r][0]);
                acc2[r][1] = fma2(pd, vv.y, acc2[r][1]);
            }
        }
    }

#pragma unroll
    for (int r = 0; r < 4; r++) {
        float inv = 1.f / lrow[r];
        float o0, o1, o2, o3;
        unpack2(acc2[r][0], o0, o1);
        unpack2(acc2[r][1], o2, o3);
        int gi = i0 + ty * 4 + r;
        float4 o = make_float4(o0 * inv, o1 * inv, o2 * inv, o3 * inv);
        *(float4*)&g_C[((size_t)b * S_ + gi) * D_ + h * DH_ + tx * 4] = o;
    }
}

// ===========================================================================
extern "C" void kernel_launch(void* const* d_in, const int* in_sizes, int n_in,
                              void* d_out, int out_size)
{
    (void)in_sizes; (void)n_in; (void)out_size;
    const float* queries = (const float*)d_in[0];
    const float* keys    = (const float*)d_in[1];
    const float* values  = (const float*)d_in[2];
    // d_in[3] = mask: causal, implemented analytically
    const float* Wq = (const float*)d_in[4];
    const float* Wk = (const float*)d_in[5];
    const float* Wv = (const float*)d_in[6];
    const float* Wo = (const float*)d_in[7];
    const float* rel = (const float*)d_in[8];

    float *Qp, *Kp, *Vp, *Cp;
    cudaGetSymbolAddress((void**)&Qp, g_Q);
    cudaGetSymbolAddress((void**)&Kp, g_K);
    cudaGetSymbolAddress((void**)&Vp, g_V);
    cudaGetSymbolAddress((void**)&Cp, g_C);

    cudaFuncSetAttribute(gemm_mma, cudaFuncAttributeMaxDynamicSharedMemorySize,
                         TCG_SMEM);
    cudaFuncSetAttribute(attn_kernel, cudaFuncAttributeMaxDynamicSharedMemorySize,
                         ATTN_SMEM_BYTES);

    // fused Q/K/V projections (tensor-core tf32 mma.sync)
    gemm_mma<<<dim3(4, 32, 3), 256, TCG_SMEM>>>(
        queries, keys, values, Wq, Wk, Wv, Qp, Kp, Vp, 1);

    attn_kernel<<<dim3(16, H_, B_), 256, ATTN_SMEM_BYTES>>>(Qp, Kp, Vp, rel, Cp);

    // output projection
    gemm_mma<<<dim3(4, 32, 1), 256, TCG_SMEM>>>(
        Cp, Cp, Cp, Wo, Wo, Wo, (float*)d_out, (float*)d_out, (float*)d_out, 0);
}

// round 10
// speedup vs baseline: 1.3627x; 1.3627x over previous
#include <cuda_runtime.h>
#include <math.h>
#include <stdint.h>

#define B_  4
#define S_  1024
#define D_  512
#define H_  8
#define DH_ 64
#define SCALE_ 0.125f   // DH^-0.5

typedef unsigned long long u64;

// Scratch (device globals: allocation-free per harness rules)
__device__ float g_Q[B_*H_*S_*DH_];
__device__ float g_K[B_*H_*S_*DH_];
__device__ float g_V[B_*H_*S_*DH_];
__device__ float g_C[B_*S_*D_];

// ---------------------------------------------------------------------------
// Packed f32x2 helpers (Blackwell sm_103a)
// ---------------------------------------------------------------------------
__device__ __forceinline__ u64 pack2(float lo, float hi) {
    u64 r; asm("mov.b64 %0, {%1, %2};" : "=l"(r) : "f"(lo), "f"(hi)); return r;
}
__device__ __forceinline__ u64 dup2(float x) { return pack2(x, x); }
__device__ __forceinline__ void unpack2(u64 v, float& lo, float& hi) {
    asm("mov.b64 {%0, %1}, %2;" : "=f"(lo), "=f"(hi) : "l"(v));
}
__device__ __forceinline__ u64 fma2(u64 a, u64 b, u64 c) {
    u64 d; asm("fma.rn.f32x2 %0, %1, %2, %3;" : "=l"(d) : "l"(a), "l"(b), "l"(c));
    return d;
}
__device__ __forceinline__ u64 mul2(u64 a, u64 b) {
    u64 d; asm("mul.rn.f32x2 %0, %1, %2;" : "=l"(d) : "l"(a), "l"(b)); return d;
}

// ---------------------------------------------------------------------------
// mma.sync tf32 helpers (baseline sm_80+ PTX — compiles at compute_103)
// ---------------------------------------------------------------------------
__device__ __forceinline__ uint32_t f2tf32(float v) {
    uint32_t t; asm("cvt.rna.tf32.f32 %0, %1;" : "=r"(t) : "f"(v)); return t;
}
__device__ __forceinline__ void mma_tf32(float* c, const uint32_t* a,
                                         uint32_t b0, uint32_t b1) {
    asm volatile(
        "mma.sync.aligned.m16n8k8.row.col.f32.tf32.tf32.f32 "
        "{%0,%1,%2,%3}, {%4,%5,%6,%7}, {%8,%9}, {%0,%1,%2,%3};"
        : "+f"(c[0]), "+f"(c[1]), "+f"(c[2]), "+f"(c[3])
        : "r"(a[0]), "r"(a[1]), "r"(a[2]), "r"(a[3]), "r"(b0), "r"(b1));
}

// ===========================================================================
// SIMT f32x2 GEMM (proven R4): out = X[4096,512] @ W[512,512], headed scatter.
// ===========================================================================
#define NCH 32   // 512 / 16

__global__ __launch_bounds__(256) void gemm_f2(
    const float* __restrict__ X0, const float* __restrict__ X1,
    const float* __restrict__ X2,
    const float* __restrict__ W0, const float* __restrict__ W1,
    const float* __restrict__ W2,
    float* __restrict__ O0, float* __restrict__ O1,
    float* __restrict__ O2, int headed)
{
    __shared__ __align__(16) float As[2][16][132];
    __shared__ __align__(16) float Bs[2][16][132];

    const int z = blockIdx.z;
    const float* X = (z == 0) ? X0 : (z == 1) ? X1 : X2;
    const float* W = (z == 0) ? W0 : (z == 1) ? W1 : W2;
    float* O       = (z == 0) ? O0 : (z == 1) ? O1 : O2;

    const int m0 = blockIdx.y * 128;
    const int n0 = blockIdx.x * 128;
    const int tid = threadIdx.x;
    const int ty = tid >> 4, tx = tid & 15;

    const int a_row0 = tid >> 2, a_kq = (tid & 3) * 4;
    const int b_k0 = tid >> 5,   b_n = (tid & 31) * 4;

    u64 acc[8][4];
#pragma unroll
    for (int r = 0; r < 8; r++)
#pragma unroll
        for (int cp = 0; cp < 4; cp++) acc[r][cp] = 0ull;

    float4 ra[2], rb[2];
#pragma unroll
    for (int it = 0; it < 2; it++) {
        ra[it] = *(const float4*)&X[(m0 + a_row0 + it * 64) * 512 + a_kq];
        rb[it] = *(const float4*)&W[(b_k0 + it * 8) * 512 + n0 + b_n];
    }
#pragma unroll
    for (int it = 0; it < 2; it++) {
        int row = a_row0 + it * 64;
        As[0][a_kq + 0][row] = ra[it].x;
        As[0][a_kq + 1][row] = ra[it].y;
        As[0][a_kq + 2][row] = ra[it].z;
        As[0][a_kq + 3][row] = ra[it].w;
        *(float4*)&Bs[0][b_k0 + it * 8][b_n] = rb[it];
    }

    for (int c = 0; c < NCH; c++) {
        __syncthreads();
        const int buf = c & 1;
        if (c < NCH - 1) {
            const int k0 = (c + 1) * 16;
#pragma unroll
            for (int it = 0; it < 2; it++) {
                ra[it] = *(const float4*)&X[(m0 + a_row0 + it * 64) * 512 + k0 + a_kq];
                rb[it] = *(const float4*)&W[(k0 + b_k0 + it * 8) * 512 + n0 + b_n];
            }
        }
#pragma unroll
        for (int kk = 0; kk < 16; kk++) {
            float4 a0 = *(const float4*)&As[buf][kk][ty * 4];
            float4 a1 = *(const float4*)&As[buf][kk][64 + ty * 4];
            ulonglong2 bl = *(const ulonglong2*)&Bs[buf][kk][tx * 4];
            ulonglong2 bh = *(const ulonglong2*)&Bs[buf][kk][64 + tx * 4];
            u64 bb[4] = {bl.x, bl.y, bh.x, bh.y};
            float ar8[8] = {a0.x, a0.y, a0.z, a0.w, a1.x, a1.y, a1.z, a1.w};
#pragma unroll
            for (int r = 0; r < 8; r++) {
                u64 ad = dup2(ar8[r]);
#pragma unroll
                for (int cp = 0; cp < 4; cp++)
                    acc[r][cp] = fma2(ad, bb[cp], acc[r][cp]);
            }
        }
        if (c < NCH - 1) {
            const int nb = (c + 1) & 1;
#pragma unroll
            for (int it = 0; it < 2; it++) {
                int row = a_row0 + it * 64;
                As[nb][a_kq + 0][row] = ra[it].x;
                As[nb][a_kq + 1][row] = ra[it].y;
                As[nb][a_kq + 2][row] = ra[it].z;
                As[nb][a_kq + 3][row] = ra[it].w;
                *(float4*)&Bs[nb][b_k0 + it * 8][b_n] = rb[it];
            }
        }
    }

#pragma unroll
    for (int r = 0; r < 8; r++) {
        float c0, c1, c2, c3, c4, c5, c6, c7;
        unpack2(acc[r][0], c0, c1); unpack2(acc[r][1], c2, c3);
        unpack2(acc[r][2], c4, c5); unpack2(acc[r][3], c6, c7);
        float4 lo = make_float4(c0, c1, c2, c3);
        float4 hi = make_float4(c4, c5, c6, c7);
        int row = ((r >> 2) * 64) + ty * 4 + (r & 3);
        int m = m0 + row;
        if (headed) {
            int bi = m >> 10, si = m & 1023, h0 = n0 >> 6;
            *(float4*)&O[((size_t)(bi * H_ + h0) * S_ + si) * DH_ + tx * 4] = lo;
            *(float4*)&O[((size_t)(bi * H_ + h0 + 1) * S_ + si) * DH_ + tx * 4] = hi;
        } else {
            *(float4*)&O[(size_t)m * 512 + n0 + tx * 4] = lo;
            *(float4*)&O[(size_t)m * 512 + n0 + 64 + tx * 4] = hi;
        }
    }
}

// ===========================================================================
// Fused causal attention, rel bias via skew identity:
//   bias(i,j) = q_i . rel[:, S-1-i+j]   (j <= i)
// S-computation on tensor cores (mma.sync tf32):
//   QE = Q @ R_window  (64x128), then S = Q@K^T + gather QE[i, 63-il+jl]
// Softmax + PV stay exact fp32 SIMT (proven).
//
// Smem map (4B words), total 25856 words = 103424 B:
//   [0      .. 4352)  Ks   : K tile tf32, natural [j][68]
//   [4352   .. 8704)  Vs   : V tile fp32, natural [j][68]
//   [8704   ..17152)  QEs  : QE fp32 [i][132]   (start: Q tf32 staging [i][68])
//   [17152  ..25856)  Rt   : R window tf32 [lc][68] rotated   (alias: Ps fp32 [i][68])
// ===========================================================================
#define KS_OFF 0
#define VS_OFF 4352
#define QE_OFF 8704
#define RT_OFF 17152
#define PS_OFF RT_OFF
#define ATTN_SMEM_BYTES (25856 * 4)

__global__ __launch_bounds__(256, 2) void attn_kernel(const float* __restrict__ Q,
                                                      const float* __restrict__ K,
                                                      const float* __restrict__ V,
                                                      const float* __restrict__ rel,
                                                      float* __restrict__ ctx)
{
    extern __shared__ __align__(16) float smf[];
    uint32_t* smu = (uint32_t*)smf;

    const int qt = (int)gridDim.x - 1 - (int)blockIdx.x;  // heavy tiles first
    const int h = blockIdx.y, b = blockIdx.z;
    const int i0 = qt * 64;
    const int tid = threadIdx.x;
    const int ty = tid >> 4, tx = tid & 15;
    const int wid = tid >> 5, lane = tid & 31;
    const int wm = wid & 3, wn = wid >> 2;   // warp tile: rows wm*16; cols wn*32 (S) / wn*64 (QE)
    const int g = lane >> 2, q = lane & 3;
    const int R0 = wm * 16;

    const float* Qb = Q + (size_t)(b * H_ + h) * S_ * DH_;
    const float* Kb = K + (size_t)(b * H_ + h) * S_ * DH_;
    const float* Vb = V + (size_t)(b * H_ + h) * S_ * DH_;
    const float* relh = rel + (size_t)h * DH_ * S_;

    // ---- Load Q tile (tf32) into staging (QE region), natural [i][68]
#pragma unroll
    for (int rep = 0; rep < 4; rep++) {
        int lin = rep * 256 + tid;
        int i = lin >> 4, sd = (lin & 15) * 4;
        float4 v = *(const float4*)&Qb[(i0 + i) * DH_ + sd];
        uint4 t = make_uint4(f2tf32(v.x), f2tf32(v.y), f2tf32(v.z), f2tf32(v.w));
        *(uint4*)&smu[QE_OFF + i * 68 + sd] = t;
    }
    __syncthreads();

    // ---- Build persistent A-fragments of Q (rows R0..R0+15, all 64 d)
    uint32_t afr[8][4];
#pragma unroll
    for (int k8 = 0; k8 < 8; k8++) {
        afr[k8][0] = smu[QE_OFF + (R0 + g) * 68 + k8 * 8 + q];
        afr[k8][1] = smu[QE_OFF + (R0 + 8 + g) * 68 + k8 * 8 + q];
        afr[k8][2] = smu[QE_OFF + (R0 + g) * 68 + k8 * 8 + 4 + q];
        afr[k8][3] = smu[QE_OFF + (R0 + 8 + g) * 68 + k8 * 8 + 4 + q];
    }
    __syncthreads();

    float mrow[4], lrow[4];
    u64 acc2[4][2];
#pragma unroll
    for (int r = 0; r < 4; r++) {
        mrow[r] = -1e30f;
        lrow[r] = 0.f;
        acc2[r][0] = 0ull; acc2[r][1] = 0ull;
    }

    for (int jt = 0; jt <= qt; jt++) {
        const int j0 = jt * 64;
        __syncthreads();   // protect Ps/Vs reads of previous iteration

        // ---- Load K (tf32 natural), V (fp32 natural)
#pragma unroll
        for (int rep = 0; rep < 4; rep++) {
            int lin = rep * 256 + tid;
            int j = lin >> 4, sd = (lin & 15) * 4;
            float4 kv = *(const float4*)&Kb[(j0 + j) * DH_ + sd];
            uint4 t = make_uint4(f2tf32(kv.x), f2tf32(kv.y), f2tf32(kv.z), f2tf32(kv.w));
            *(uint4*)&smu[KS_OFF + j * 68 + sd] = t;
            float4 vv = *(const float4*)&Vb[(j0 + j) * DH_ + sd];
            *(float4*)&smf[VS_OFF + j * 68 + sd] = vv;
        }
        // ---- Load R window (tf32, transposed + rotated): Rt[lc][(d+lc)&63]
        {
            const int cb = S_ - 64 - i0 + j0;
#pragma unroll
            for (int rep = 0; rep < 8; rep++) {
                int idx = rep * 256 + tid;
                int d = idx >> 5, lc = (idx & 31) * 4;
                int c = cb + lc;
                float4 rv;
                if (c + 3 < S_) {
                    rv = *(const float4*)&relh[d * S_ + c];
                } else {
                    rv.x = (c + 0 < S_) ? relh[d * S_ + c + 0] : 0.f;
                    rv.y = (c + 1 < S_) ? relh[d * S_ + c + 1] : 0.f;
                    rv.z = (c + 2 < S_) ? relh[d * S_ + c + 2] : 0.f;
                    rv.w = (c + 3 < S_) ? relh[d * S_ + c + 3] : 0.f;
                }
                float va[4] = {rv.x, rv.y, rv.z, rv.w};
#pragma unroll
                for (int jj = 0; jj < 4; jj++)
                    smu[RT_OFF + (lc + jj) * 68 + ((d + lc + jj) & 63)] = f2tf32(va[jj]);
            }
        }
        __syncthreads();

        // ---- QE = Q @ R_window: warp covers rows R0..+16, cols wn*64..+64
#pragma unroll
        for (int nt = 0; nt < 8; nt++) {
            const int L0 = wn * 64 + nt * 8;
            const int lcb = L0 + g;
            const int rbase = RT_OFF + lcb * 68;
            float c4[4] = {0.f, 0.f, 0.f, 0.f};
#pragma unroll
            for (int k8 = 0; k8 < 8; k8++) {
                int d0 = k8 * 8 + q;
                uint32_t b0 = smu[rbase + ((d0 + lcb) & 63)];
                uint32_t b1 = smu[rbase + ((d0 + 4 + lcb) & 63)];
                mma_tf32(c4, afr[k8], b0, b1);
            }
            *(float2*)&smf[QE_OFF + (R0 + g) * 132 + L0 + q * 2] =
                make_float2(c4[0], c4[1]);
            *(float2*)&smf[QE_OFF + (R0 + 8 + g) * 132 + L0 + q * 2] =
                make_float2(c4[2], c4[3]);
        }
        __syncthreads();

        // ---- S = Q @ K^T + gather(QE): warp covers rows R0..+16, cols wn*32..+32
#pragma unroll
        for (int nt = 0; nt < 4; nt++) {
            const int N0 = wn * 32 + nt * 8;
            float c4[4] = {0.f, 0.f, 0.f, 0.f};
#pragma unroll
            for (int k8 = 0; k8 < 8; k8++) {
                uint32_t b0 = smu[KS_OFF + (N0 + g) * 68 + k8 * 8 + q];
                uint32_t b1 = smu[KS_OFF + (N0 + g) * 68 + k8 * 8 + 4 + q];
                mma_tf32(c4, afr[k8], b0, b1);
            }
            const int row = R0 + g, col = N0 + q * 2;
            c4[0] += smf[QE_OFF + row * 132 + (63 - row + col)];
            c4[1] += smf[QE_OFF + row * 132 + (64 - row + col)];
            c4[2] += smf[QE_OFF + (row + 8) * 132 + (55 - row + col)];
            c4[3] += smf[QE_OFF + (row + 8) * 132 + (56 - row + col)];
            *(float2*)&smf[PS_OFF + row * 68 + col] = make_float2(c4[0], c4[1]);
            *(float2*)&smf[PS_OFF + (row + 8) * 68 + col] = make_float2(c4[2], c4[3]);
        }
        __syncthreads();

        // ---- SIMT: read raw S, mask+scale, online softmax, write P back
        float s[4][4];
#pragma unroll
        for (int r = 0; r < 4; r++) {
            float4 sv = *(const float4*)&smf[PS_OFF + (ty * 4 + r) * 68 + tx * 4];
            s[r][0] = sv.x; s[r][1] = sv.y; s[r][2] = sv.z; s[r][3] = sv.w;
        }
#pragma unroll
        for (int r = 0; r < 4; r++) {
            int gi = i0 + ty * 4 + r;
#pragma unroll
            for (int c = 0; c < 4; c++) {
                int gj = j0 + tx * 4 + c;
                s[r][c] = (gj > gi) ? -INFINITY : s[r][c] * SCALE_;
            }
        }
#pragma unroll
        for (int r = 0; r < 4; r++) {
            float tm = fmaxf(fmaxf(s[r][0], s[r][1]), fmaxf(s[r][2], s[r][3]));
#pragma unroll
            for (int o = 8; o; o >>= 1)
                tm = fmaxf(tm, __shfl_xor_sync(0xffffffffu, tm, o, 16));
            float nm = fmaxf(mrow[r], tm);
            float al = __expf(mrow[r] - nm);
            float p0 = __expf(s[r][0] - nm);
            float p1 = __expf(s[r][1] - nm);
            float p2 = __expf(s[r][2] - nm);
            float p3 = __expf(s[r][3] - nm);
            float rs = p0 + p1 + p2 + p3;
#pragma unroll
            for (int o = 8; o; o >>= 1)
                rs += __shfl_xor_sync(0xffffffffu, rs, o, 16);
            lrow[r] = lrow[r] * al + rs;
            mrow[r] = nm;
            u64 al2 = dup2(al);
            acc2[r][0] = mul2(acc2[r][0], al2);
            acc2[r][1] = mul2(acc2[r][1], al2);
            *(float4*)&smf[PS_OFF + (ty * 4 + r) * 68 + tx * 4] =
                make_float4(p0, p1, p2, p3);
        }
        __syncthreads();

        // ---- PV: acc += P @ V  (exact fp32, f32x2 packed)
#pragma unroll 4
        for (int j4 = 0; j4 < 64; j4 += 4) {
            float4 pr[4];
#pragma unroll
            for (int r = 0; r < 4; r++)
                pr[r] = *(const float4*)&smf[PS_OFF + (ty * 4 + r) * 68 + j4];
            float pm[4][4];
#pragma unroll
            for (int r = 0; r < 4; r++) {
                pm[r][0] = pr[r].x; pm[r][1] = pr[r].y;
                pm[r][2] = pr[r].z; pm[r][3] = pr[r].w;
            }
#pragma unroll
            for (int jj = 0; jj < 4; jj++) {
                ulonglong2 vv = *(const ulonglong2*)&smf[VS_OFF + (j4 + jj) * 68 + tx * 4];
#pragma unroll
                for (int r = 0; r < 4; r++) {
                    u64 pd = dup2(pm[r][jj]);
                    acc2[r][0] = fma2(pd, vv.x, acc2[r][0]);
                    acc2[r][1] = fma2(pd, vv.y, acc2[r][1]);
                }
            }
        }
    }

    // ---- Write ctx in [B, S, H*DH] layout for the output projection GEMM
#pragma unroll
    for (int r = 0; r < 4; r++) {
        float inv = 1.f / lrow[r];
        float o0, o1, o2, o3;
        unpack2(acc2[r][0], o0, o1);
        unpack2(acc2[r][1], o2, o3);
        int gi = i0 + ty * 4 + r;
        float4 o = make_float4(o0 * inv, o1 * inv, o2 * inv, o3 * inv);
        *(float4*)&g_C[((size_t)b * S_ + gi) * D_ + h * DH_ + tx * 4] = o;
    }
}

// ===========================================================================
extern "C" void kernel_launch(void* const* d_in, const int* in_sizes, int n_in,
                              void* d_out, int out_size)
{
    (void)in_sizes; (void)n_in; (void)out_size;
    const float* queries = (const float*)d_in[0];
    const float* keys    = (const float*)d_in[1];
    const float* values  = (const float*)d_in[2];
    // d_in[3] = mask: causal, implemented analytically
    const float* Wq = (const float*)d_in[4];
    const float* Wk = (const float*)d_in[5];
    const float* Wv = (const float*)d_in[6];
    const float* Wo = (const float*)d_in[7];
    const float* rel = (const float*)d_in[8];

    float *Qp, *Kp, *Vp, *Cp;
    cudaGetSymbolAddress((void**)&Qp, g_Q);
    cudaGetSymbolAddress((void**)&Kp, g_K);
    cudaGetSymbolAddress((void**)&Vp, g_V);
    cudaGetSymbolAddress((void**)&Cp, g_C);

    cudaFuncSetAttribute(attn_kernel, cudaFuncAttributeMaxDynamicSharedMemorySize,
                         ATTN_SMEM_BYTES);

    // fused Q/K/V projections (proven f32x2 SIMT, exact fp32)
    gemm_f2<<<dim3(4, 32, 3), 256>>>(
        queries, keys, values, Wq, Wk, Wv, Qp, Kp, Vp, 1);

    // attention: tensor-core S (tf32) + exact fp32 softmax/PV
    attn_kernel<<<dim3(16, H_, B_), 256, ATTN_SMEM_BYTES>>>(Qp, Kp, Vp, rel, Cp);

    // output projection (exact fp32)
    gemm_f2<<<dim3(4, 32, 1), 256>>>(
        Cp, Cp, Cp, Wo, Wo, Wo, (float*)d_out, (float*)d_out, (float*)d_out, 0);
}